// round 4
// baseline (speedup 1.0000x reference)
#include <cuda_runtime.h>
#include <math.h>

// Problem shape (fixed by setup_inputs)
#define BB 8
#define CC 256
#define NN 2048
#define KK 24
#define ROWS (BB * CC * NN)        // 4,194,304
#define BLOCK 256
#define NBLK (ROWS / BLOCK)        // 16,384 blocks; 8 blocks per (b,c) slice
#define BN_EPS 1e-5f
#define INV_BN_COUNT (1.0f / (float)(BB * NN))   // 1/16384

// Deterministic scratch (static __device__ globals — no runtime allocation)
__device__ float g_psum[NBLK];     // per-block sum of m
__device__ float g_psq[NBLK];      // per-block sum of m^2
__device__ float g_scale[CC];      // invstd * gamma
__device__ float g_shift[CC];      // beta - mean * invstd * gamma

// ---------------------------------------------------------------------------
// Kernel 1: per-row mean over K (x2), write m into d_out, and block-partial
// BN statistics. One thread per row; row = 24 floats = 6 aligned float4s.
// Each block covers 256 consecutive rows => single channel per block.
// Note: up/down in the reference cancels exactly (e_x is a per-row scalar and
// down == e_x), so _k_anp(x) + mean_K(x) == 2 * mean_K(x).
// ---------------------------------------------------------------------------
__global__ __launch_bounds__(BLOCK) void k_reduce(const float* __restrict__ x,
                                                  float* __restrict__ m_out) {
    const int row = blockIdx.x * BLOCK + threadIdx.x;
    const float4* __restrict__ p =
        reinterpret_cast<const float4*>(x + (size_t)row * KK);

    const float4 v0 = p[0], v1 = p[1], v2 = p[2], v3 = p[3], v4 = p[4], v5 = p[5];

    float s = (v0.x + v0.y) + (v0.z + v0.w);
    s += (v1.x + v1.y) + (v1.z + v1.w);
    s += (v2.x + v2.y) + (v2.z + v2.w);
    s += (v3.x + v3.y) + (v3.z + v3.w);
    s += (v4.x + v4.y) + (v4.z + v4.w);
    s += (v5.x + v5.y) + (v5.z + v5.w);

    const float m = s * (2.0f / (float)KK);
    m_out[row] = m;

    // Deterministic block reduction of (m, m^2): warp shuffle + smem.
    float sm = m;
    float sq = m * m;
    #pragma unroll
    for (int off = 16; off > 0; off >>= 1) {
        sm += __shfl_down_sync(0xFFFFFFFFu, sm, off);
        sq += __shfl_down_sync(0xFFFFFFFFu, sq, off);
    }
    __shared__ float sh_m[BLOCK / 32];
    __shared__ float sh_q[BLOCK / 32];
    const int lane = threadIdx.x & 31;
    const int wid  = threadIdx.x >> 5;
    if (lane == 0) { sh_m[wid] = sm; sh_q[wid] = sq; }
    __syncthreads();
    if (wid == 0) {
        float tm = (lane < BLOCK / 32) ? sh_m[lane] : 0.0f;
        float tq = (lane < BLOCK / 32) ? sh_q[lane] : 0.0f;
        #pragma unroll
        for (int off = 4; off > 0; off >>= 1) {
            tm += __shfl_down_sync(0xFFFFFFFFu, tm, off);
            tq += __shfl_down_sync(0xFFFFFFFFu, tq, off);
        }
        if (lane == 0) {
            g_psum[blockIdx.x] = tm;
            g_psq[blockIdx.x]  = tq;
        }
    }
}

// ---------------------------------------------------------------------------
// Kernel 2: fold 64 block-partials per channel into fused scale/shift.
// Block layout from k_reduce: blockIdx = (b*CC + c)*8 + j, b in [0,8), j in [0,8).
// One block of 256 threads; thread c handles channel c. Deterministic order.
// ---------------------------------------------------------------------------
__global__ __launch_bounds__(CC) void k_stats(const float* __restrict__ gamma,
                                              const float* __restrict__ beta) {
    const int c = threadIdx.x;
    float sm = 0.0f, sq = 0.0f;
    #pragma unroll
    for (int b = 0; b < BB; b++) {
        const int base = (b * CC + c) * 8;
        #pragma unroll
        for (int j = 0; j < 8; j++) {
            sm += g_psum[base + j];
            sq += g_psq[base + j];
        }
    }
    const float mean = sm * INV_BN_COUNT;
    const float var  = sq * INV_BN_COUNT - mean * mean;   // biased, as torch BN
    const float scale = rsqrtf(var + BN_EPS) * gamma[c];
    g_scale[c] = scale;
    g_shift[c] = beta[c] - mean * scale;
}

// ---------------------------------------------------------------------------
// Kernel 3: in-place fused BN affine + exact GELU over d_out, float4-vectorized.
// 4 consecutive elements share a channel (NN % 4 == 0).
// ---------------------------------------------------------------------------
__device__ __forceinline__ float gelu_exact(float y) {
    return 0.5f * y * (1.0f + erff(y * 0.70710678118654752f));
}

__global__ __launch_bounds__(BLOCK) void k_bn_gelu(float* __restrict__ m_io) {
    const int i4 = blockIdx.x * BLOCK + threadIdx.x;   // float4 index
    const int c  = (i4 >> 9) & (CC - 1);               // (i4*4 / NN) % CC
    const float scale = g_scale[c];
    const float shift = g_shift[c];

    float4 v = reinterpret_cast<float4*>(m_io)[i4];
    v.x = gelu_exact(fmaf(v.x, scale, shift));
    v.y = gelu_exact(fmaf(v.y, scale, shift));
    v.z = gelu_exact(fmaf(v.z, scale, shift));
    v.w = gelu_exact(fmaf(v.w, scale, shift));
    reinterpret_cast<float4*>(m_io)[i4] = v;
}

// ---------------------------------------------------------------------------
extern "C" void kernel_launch(void* const* d_in, const int* in_sizes, int n_in,
                              void* d_out, int out_size) {
    const float* x     = (const float*)d_in[0];   // [B, C, N, K] f32
    const float* gamma = (const float*)d_in[1];   // [C]
    const float* beta  = (const float*)d_in[2];   // [C]
    float* out = (float*)d_out;                   // [B, C, N] f32

    k_reduce<<<NBLK, BLOCK>>>(x, out);
    k_stats<<<1, CC>>>(gamma, beta);
    k_bn_gelu<<<ROWS / 4 / BLOCK, BLOCK>>>(out);
}

// round 5
// speedup vs baseline: 1.0163x; 1.0163x over previous
#include <cuda_runtime.h>
#include <math.h>

// Problem shape (fixed by setup_inputs)
#define BB 8
#define CC 256
#define NN 2048
#define KK 24
#define ROWS (BB * CC * NN)        // 4,194,304
#define BLOCK 256
#define NBLK (ROWS / BLOCK)        // 16,384 blocks; 8 blocks per (b,c) slice
#define BN_EPS 1e-5f
#define INV_BN_COUNT (1.0f / (float)(BB * NN))   // 1/16384

// Deterministic scratch (static __device__ globals — no runtime allocation)
__device__ float g_psum[NBLK];     // per-block sum of m
__device__ float g_psq[NBLK];      // per-block sum of m^2
__device__ float g_scale[CC];      // invstd * gamma
__device__ float g_shift[CC];      // beta - mean * invstd * gamma

// ---------------------------------------------------------------------------
// Kernel 1: per-row mean over K (x2), write m into d_out, and block-partial
// BN statistics. One thread per row; row = 24 floats = 6 aligned float4s.
// Each block covers 256 consecutive rows => single channel per block.
// Note: up/down in the reference cancels exactly (e_x is a per-row scalar and
// down == e_x), so _k_anp(x) + mean_K(x) == 2 * mean_K(x).
// ---------------------------------------------------------------------------
__global__ __launch_bounds__(BLOCK) void k_reduce(const float* __restrict__ x,
                                                  float* __restrict__ m_out) {
    const int row = blockIdx.x * BLOCK + threadIdx.x;
    const float4* __restrict__ p =
        reinterpret_cast<const float4*>(x + (size_t)row * KK);

    const float4 v0 = p[0], v1 = p[1], v2 = p[2], v3 = p[3], v4 = p[4], v5 = p[5];

    float s = (v0.x + v0.y) + (v0.z + v0.w);
    s += (v1.x + v1.y) + (v1.z + v1.w);
    s += (v2.x + v2.y) + (v2.z + v2.w);
    s += (v3.x + v3.y) + (v3.z + v3.w);
    s += (v4.x + v4.y) + (v4.z + v4.w);
    s += (v5.x + v5.y) + (v5.z + v5.w);

    const float m = s * (2.0f / (float)KK);
    m_out[row] = m;

    // Deterministic block reduction of (m, m^2): warp shuffle + smem.
    float sm = m;
    float sq = m * m;
    #pragma unroll
    for (int off = 16; off > 0; off >>= 1) {
        sm += __shfl_down_sync(0xFFFFFFFFu, sm, off);
        sq += __shfl_down_sync(0xFFFFFFFFu, sq, off);
    }
    __shared__ float sh_m[BLOCK / 32];
    __shared__ float sh_q[BLOCK / 32];
    const int lane = threadIdx.x & 31;
    const int wid  = threadIdx.x >> 5;
    if (lane == 0) { sh_m[wid] = sm; sh_q[wid] = sq; }
    __syncthreads();
    if (wid == 0) {
        float tm = (lane < BLOCK / 32) ? sh_m[lane] : 0.0f;
        float tq = (lane < BLOCK / 32) ? sh_q[lane] : 0.0f;
        #pragma unroll
        for (int off = 4; off > 0; off >>= 1) {
            tm += __shfl_down_sync(0xFFFFFFFFu, tm, off);
            tq += __shfl_down_sync(0xFFFFFFFFu, tq, off);
        }
        if (lane == 0) {
            g_psum[blockIdx.x] = tm;
            g_psq[blockIdx.x]  = tq;
        }
    }
}

// ---------------------------------------------------------------------------
// Kernel 2: fold 64 block-partials per channel into fused scale/shift.
// Block layout from k_reduce: blockIdx = (b*CC + c)*8 + j, b in [0,8), j in [0,8).
// One block of 256 threads; thread c handles channel c. Deterministic order.
// ---------------------------------------------------------------------------
__global__ __launch_bounds__(CC) void k_stats(const float* __restrict__ gamma,
                                              const float* __restrict__ beta) {
    const int c = threadIdx.x;
    float sm = 0.0f, sq = 0.0f;
    #pragma unroll
    for (int b = 0; b < BB; b++) {
        const int base = (b * CC + c) * 8;
        #pragma unroll
        for (int j = 0; j < 8; j++) {
            sm += g_psum[base + j];
            sq += g_psq[base + j];
        }
    }
    const float mean = sm * INV_BN_COUNT;
    const float var  = sq * INV_BN_COUNT - mean * mean;   // biased, as torch BN
    const float scale = rsqrtf(var + BN_EPS) * gamma[c];
    g_scale[c] = scale;
    g_shift[c] = beta[c] - mean * scale;
}

// ---------------------------------------------------------------------------
// Kernel 3: in-place fused BN affine + exact GELU over d_out, float4-vectorized.
// 4 consecutive elements share a channel (NN % 4 == 0).
// ---------------------------------------------------------------------------
__device__ __forceinline__ float gelu_exact(float y) {
    return 0.5f * y * (1.0f + erff(y * 0.70710678118654752f));
}

__global__ __launch_bounds__(BLOCK) void k_bn_gelu(float* __restrict__ m_io) {
    const int i4 = blockIdx.x * BLOCK + threadIdx.x;   // float4 index
    const int c  = (i4 >> 9) & (CC - 1);               // (i4*4 / NN) % CC
    const float scale = g_scale[c];
    const float shift = g_shift[c];

    float4 v = reinterpret_cast<float4*>(m_io)[i4];
    v.x = gelu_exact(fmaf(v.x, scale, shift));
    v.y = gelu_exact(fmaf(v.y, scale, shift));
    v.z = gelu_exact(fmaf(v.z, scale, shift));
    v.w = gelu_exact(fmaf(v.w, scale, shift));
    reinterpret_cast<float4*>(m_io)[i4] = v;
}

// ---------------------------------------------------------------------------
extern "C" void kernel_launch(void* const* d_in, const int* in_sizes, int n_in,
                              void* d_out, int out_size) {
    const float* x     = (const float*)d_in[0];   // [B, C, N, K] f32
    const float* gamma = (const float*)d_in[1];   // [C]
    const float* beta  = (const float*)d_in[2];   // [C]
    float* out = (float*)d_out;                   // [B, C, N] f32

    k_reduce<<<NBLK, BLOCK>>>(x, out);
    k_stats<<<1, CC>>>(gamma, beta);
    k_bn_gelu<<<ROWS / 4 / BLOCK, BLOCK>>>(out);
}

// round 7
// speedup vs baseline: 1.0248x; 1.0084x over previous
#include <cuda_runtime.h>
#include <math.h>

// Problem shape (fixed by setup_inputs)
#define BB 8
#define CC 256
#define NN 2048
#define KK 24
#define ROWS (BB * CC * NN)        // 4,194,304
#define BLOCK 256
#define RPB 256                    // rows per block
#define F4PB (RPB * KK / 4)        // 1536 float4s per block
#define NBLK (ROWS / RPB)          // 16,384 blocks; 8 blocks per (b,c) slice
#define BN_EPS 1e-5f
#define INV_BN_COUNT (1.0f / (float)(BB * NN))   // 1/16384

// Deterministic scratch (static __device__ globals — no runtime allocation)
__device__ float g_psum[NBLK];     // per-block sum of m
__device__ float g_psq[NBLK];      // per-block sum of m^2
__device__ float g_scale[CC];      // invstd * gamma
__device__ float g_shift[CC];      // beta - mean * invstd * gamma

// ---------------------------------------------------------------------------
// Kernel 1: per-row mean over K (x2) with PERFECTLY COALESCED loads.
// Each block owns 256 consecutive rows = 24 KB = 1536 float4, loaded as
// 6 fully-contiguous 4 KB sweeps (4 lines / LDG wavefront — L1-optimal).
// Per-float4 partial sums staged in smem, then thread t folds the 6 partials
// of row t (flat float4s [6t, 6t+6)). Block = one channel (NN % RPB == 0).
// Note: up/down in the reference cancels exactly (e_x is a per-row scalar and
// down == e_x), so _k_anp(x) + mean_K(x) == 2 * mean_K(x).
// ---------------------------------------------------------------------------
__global__ __launch_bounds__(BLOCK) void k_reduce(const float* __restrict__ x,
                                                  float* __restrict__ m_out) {
    __shared__ float ps[F4PB];                  // 6 KB partial sums
    const float4* __restrict__ p =
        reinterpret_cast<const float4*>(x) + (size_t)blockIdx.x * F4PB;
    const int t = threadIdx.x;

    #pragma unroll
    for (int j = 0; j < 6; j++) {
        const float4 v = p[t + BLOCK * j];      // coalesced: 4 KB contiguous
        ps[t + BLOCK * j] = (v.x + v.y) + (v.z + v.w);
    }
    __syncthreads();

    // Row t's 24 elements are flat float4s [6t, 6t+6).
    const int b6 = 6 * t;
    float s = ((ps[b6] + ps[b6 + 1]) + (ps[b6 + 2] + ps[b6 + 3]))
            + (ps[b6 + 4] + ps[b6 + 5]);
    const float m = s * (2.0f / (float)KK);
    m_out[blockIdx.x * RPB + t] = m;

    // Deterministic block reduction of (m, m^2): warp shuffle + smem.
    float sm = m;
    float sq = m * m;
    #pragma unroll
    for (int off = 16; off > 0; off >>= 1) {
        sm += __shfl_down_sync(0xFFFFFFFFu, sm, off);
        sq += __shfl_down_sync(0xFFFFFFFFu, sq, off);
    }
    __shared__ float sh_m[BLOCK / 32];
    __shared__ float sh_q[BLOCK / 32];
    const int lane = t & 31;
    const int wid  = t >> 5;
    if (lane == 0) { sh_m[wid] = sm; sh_q[wid] = sq; }
    __syncthreads();
    if (wid == 0) {
        float tm = (lane < BLOCK / 32) ? sh_m[lane] : 0.0f;
        float tq = (lane < BLOCK / 32) ? sh_q[lane] : 0.0f;
        #pragma unroll
        for (int off = 4; off > 0; off >>= 1) {
            tm += __shfl_down_sync(0xFFFFFFFFu, tm, off);
            tq += __shfl_down_sync(0xFFFFFFFFu, tq, off);
        }
        if (lane == 0) {
            g_psum[blockIdx.x] = tm;
            g_psq[blockIdx.x]  = tq;
        }
    }
}

// ---------------------------------------------------------------------------
// Kernel 2: fold 64 block-partials per channel into fused scale/shift.
// Block layout from k_reduce: blockIdx = (b*CC + c)*8 + j, b in [0,8), j in [0,8).
// One block of 256 threads; thread c handles channel c. Deterministic order.
// ---------------------------------------------------------------------------
__global__ __launch_bounds__(CC) void k_stats(const float* __restrict__ gamma,
                                              const float* __restrict__ beta) {
    const int c = threadIdx.x;
    float sm = 0.0f, sq = 0.0f;
    #pragma unroll
    for (int b = 0; b < BB; b++) {
        const int base = (b * CC + c) * 8;
        #pragma unroll
        for (int j = 0; j < 8; j++) {
            sm += g_psum[base + j];
            sq += g_psq[base + j];
        }
    }
    const float mean = sm * INV_BN_COUNT;
    const float var  = sq * INV_BN_COUNT - mean * mean;   // biased, as torch BN
    const float scale = rsqrtf(var + BN_EPS) * gamma[c];
    g_scale[c] = scale;
    g_shift[c] = beta[c] - mean * scale;
}

// ---------------------------------------------------------------------------
// Kernel 3: in-place fused BN affine + exact GELU over d_out, float4-vectorized.
// 4 consecutive elements share a channel (NN % 4 == 0). m is L2-resident.
// ---------------------------------------------------------------------------
__device__ __forceinline__ float gelu_exact(float y) {
    return 0.5f * y * (1.0f + erff(y * 0.70710678118654752f));
}

__global__ __launch_bounds__(BLOCK) void k_bn_gelu(float* __restrict__ m_io) {
    const int i4 = blockIdx.x * BLOCK + threadIdx.x;   // float4 index
    const int c  = (i4 >> 9) & (CC - 1);               // (i4*4 / NN) % CC
    const float scale = g_scale[c];
    const float shift = g_shift[c];

    float4 v = reinterpret_cast<float4*>(m_io)[i4];
    v.x = gelu_exact(fmaf(v.x, scale, shift));
    v.y = gelu_exact(fmaf(v.y, scale, shift));
    v.z = gelu_exact(fmaf(v.z, scale, shift));
    v.w = gelu_exact(fmaf(v.w, scale, shift));
    reinterpret_cast<float4*>(m_io)[i4] = v;
}

// ---------------------------------------------------------------------------
extern "C" void kernel_launch(void* const* d_in, const int* in_sizes, int n_in,
                              void* d_out, int out_size) {
    const float* x     = (const float*)d_in[0];   // [B, C, N, K] f32
    const float* gamma = (const float*)d_in[1];   // [C]
    const float* beta  = (const float*)d_in[2];   // [C]
    float* out = (float*)d_out;                   // [B, C, N] f32

    k_reduce<<<NBLK, BLOCK>>>(x, out);
    k_stats<<<1, CC>>>(gamma, beta);
    k_bn_gelu<<<ROWS / 4 / BLOCK, BLOCK>>>(out);
}

// round 8
// speedup vs baseline: 1.0386x; 1.0134x over previous
#include <cuda_runtime.h>
#include <math.h>

// Problem shape (fixed by setup_inputs)
#define BB 8
#define CC 256
#define NN 2048
#define KK 24
#define ROWS (BB * CC * NN)        // 4,194,304
#define BLOCK 256
#define RPB 256                    // rows per block
#define F4PB (RPB * KK / 4)        // 1536 float4s per block
#define NBLK (ROWS / RPB)          // 16,384 blocks; 8 blocks per (b,c) slice
#define BN_EPS 1e-5f
#define INV_BN_COUNT (1.0f / (float)(BB * NN))   // 1/16384

// Deterministic scratch (static __device__ globals — no runtime allocation)
__device__ float g_psum[NBLK];     // per-block sum of m
__device__ float g_psq[NBLK];      // per-block sum of m^2
__device__ float g_scale[CC];      // invstd * gamma
__device__ float g_shift[CC];      // beta - mean * invstd * gamma

// ---------------------------------------------------------------------------
// Kernel 1: per-row mean over K (x2) with PERFECTLY COALESCED loads.
// Each block owns 256 consecutive rows = 24 KB = 1536 float4, loaded as
// 6 fully-contiguous 4 KB sweeps (4 lines / LDG wavefront — L1-optimal).
// Per-float4 partial sums staged in smem, then thread t folds the 6 partials
// of row t (flat float4s [6t, 6t+6)). Block = one channel (NN % RPB == 0).
// Note: up/down in the reference cancels exactly (e_x is a per-row scalar and
// down == e_x), so _k_anp(x) + mean_K(x) == 2 * mean_K(x).
// ---------------------------------------------------------------------------
__global__ __launch_bounds__(BLOCK) void k_reduce(const float* __restrict__ x,
                                                  float* __restrict__ m_out) {
    __shared__ float ps[F4PB];                  // 6 KB partial sums
    const float4* __restrict__ p =
        reinterpret_cast<const float4*>(x) + (size_t)blockIdx.x * F4PB;
    const int t = threadIdx.x;

    #pragma unroll
    for (int j = 0; j < 6; j++) {
        const float4 v = p[t + BLOCK * j];      // coalesced: 4 KB contiguous
        ps[t + BLOCK * j] = (v.x + v.y) + (v.z + v.w);
    }
    __syncthreads();

    // Row t's 24 elements are flat float4s [6t, 6t+6).
    const int b6 = 6 * t;
    float s = ((ps[b6] + ps[b6 + 1]) + (ps[b6 + 2] + ps[b6 + 3]))
            + (ps[b6 + 4] + ps[b6 + 5]);
    const float m = s * (2.0f / (float)KK);
    m_out[blockIdx.x * RPB + t] = m;

    // Deterministic block reduction of (m, m^2): warp shuffle + smem.
    float sm = m;
    float sq = m * m;
    #pragma unroll
    for (int off = 16; off > 0; off >>= 1) {
        sm += __shfl_down_sync(0xFFFFFFFFu, sm, off);
        sq += __shfl_down_sync(0xFFFFFFFFu, sq, off);
    }
    __shared__ float sh_m[BLOCK / 32];
    __shared__ float sh_q[BLOCK / 32];
    const int lane = t & 31;
    const int wid  = t >> 5;
    if (lane == 0) { sh_m[wid] = sm; sh_q[wid] = sq; }
    __syncthreads();
    if (wid == 0) {
        float tm = (lane < BLOCK / 32) ? sh_m[lane] : 0.0f;
        float tq = (lane < BLOCK / 32) ? sh_q[lane] : 0.0f;
        #pragma unroll
        for (int off = 4; off > 0; off >>= 1) {
            tm += __shfl_down_sync(0xFFFFFFFFu, tm, off);
            tq += __shfl_down_sync(0xFFFFFFFFu, tq, off);
        }
        if (lane == 0) {
            g_psum[blockIdx.x] = tm;
            g_psq[blockIdx.x]  = tq;
        }
    }
}

// ---------------------------------------------------------------------------
// Kernel 2: fold 64 block-partials per channel into fused scale/shift.
// Block layout from k_reduce: blockIdx = (b*CC + c)*8 + j, b in [0,8), j in [0,8).
// One block of 256 threads; thread c handles channel c. Deterministic order.
// ---------------------------------------------------------------------------
__global__ __launch_bounds__(CC) void k_stats(const float* __restrict__ gamma,
                                              const float* __restrict__ beta) {
    const int c = threadIdx.x;
    float sm = 0.0f, sq = 0.0f;
    #pragma unroll
    for (int b = 0; b < BB; b++) {
        const int base = (b * CC + c) * 8;
        #pragma unroll
        for (int j = 0; j < 8; j++) {
            sm += g_psum[base + j];
            sq += g_psq[base + j];
        }
    }
    const float mean = sm * INV_BN_COUNT;
    const float var  = sq * INV_BN_COUNT - mean * mean;   // biased, as torch BN
    const float scale = rsqrtf(var + BN_EPS) * gamma[c];
    g_scale[c] = scale;
    g_shift[c] = beta[c] - mean * scale;
}

// ---------------------------------------------------------------------------
// Kernel 3: in-place fused BN affine + exact GELU over d_out, float4-vectorized.
// 4 consecutive elements share a channel (NN % 4 == 0). m is L2-resident.
// ---------------------------------------------------------------------------
__device__ __forceinline__ float gelu_exact(float y) {
    return 0.5f * y * (1.0f + erff(y * 0.70710678118654752f));
}

__global__ __launch_bounds__(BLOCK) void k_bn_gelu(float* __restrict__ m_io) {
    const int i4 = blockIdx.x * BLOCK + threadIdx.x;   // float4 index
    const int c  = (i4 >> 9) & (CC - 1);               // (i4*4 / NN) % CC
    const float scale = g_scale[c];
    const float shift = g_shift[c];

    float4 v = reinterpret_cast<float4*>(m_io)[i4];
    v.x = gelu_exact(fmaf(v.x, scale, shift));
    v.y = gelu_exact(fmaf(v.y, scale, shift));
    v.z = gelu_exact(fmaf(v.z, scale, shift));
    v.w = gelu_exact(fmaf(v.w, scale, shift));
    reinterpret_cast<float4*>(m_io)[i4] = v;
}

// ---------------------------------------------------------------------------
extern "C" void kernel_launch(void* const* d_in, const int* in_sizes, int n_in,
                              void* d_out, int out_size) {
    const float* x     = (const float*)d_in[0];   // [B, C, N, K] f32
    const float* gamma = (const float*)d_in[1];   // [C]
    const float* beta  = (const float*)d_in[2];   // [C]
    float* out = (float*)d_out;                   // [B, C, N] f32

    k_reduce<<<NBLK, BLOCK>>>(x, out);
    k_stats<<<1, CC>>>(gamma, beta);
    k_bn_gelu<<<ROWS / 4 / BLOCK, BLOCK>>>(out);
}

// round 11
// speedup vs baseline: 1.1425x; 1.1000x over previous
#include <cuda_runtime.h>
#include <math.h>

// Problem shape (fixed by setup_inputs)
#define BB 8
#define CC 256
#define NN 2048
#define KK 24
#define ROWS (BB * CC * NN)        // 4,194,304
#define BLOCK 256
#define RPB 256                    // rows per block in k_reduce
#define F4PB (RPB * KK / 4)        // 1536 float4s per block
#define NBLK (ROWS / RPB)          // 16,384 blocks; 8 per (b,c) slice
#define BN_EPS 1e-5f
#define INV_BN_COUNT (1.0f / (float)(BB * NN))   // 1/16384

// Deterministic scratch (static __device__ globals — no runtime allocation)
__device__ float g_psum[NBLK];     // per-block sum of m
__device__ float g_psq[NBLK];      // per-block sum of m^2

// ---------------------------------------------------------------------------
// Kernel 1: per-row mean over K (x2) with perfectly coalesced, evict-first
// (__ldcs) loads. Each block owns 256 consecutive rows = 1536 float4, loaded
// as 6 contiguous 4 KB sweeps. Per-float4 partials staged in smem; thread t
// folds the 6 partials of row t. The x stream is single-use: .cs keeps the
// freshly written m[] resident in L2 for kernel 2.
// Note: up/down in the reference cancels exactly (e_x is a per-row scalar and
// down == e_x), so _k_anp(x) + mean_K(x) == 2 * mean_K(x).
// ---------------------------------------------------------------------------
__global__ __launch_bounds__(BLOCK) void k_reduce(const float* __restrict__ x,
                                                  float* __restrict__ m_out) {
    __shared__ float ps[F4PB];                  // 6 KB partial sums
    const float4* __restrict__ p =
        reinterpret_cast<const float4*>(x) + (size_t)blockIdx.x * F4PB;
    const int t = threadIdx.x;

    #pragma unroll
    for (int j = 0; j < 6; j++) {
        const float4 v = __ldcs(p + t + BLOCK * j);   // coalesced, evict-first
        ps[t + BLOCK * j] = (v.x + v.y) + (v.z + v.w);
    }
    __syncthreads();

    // Row t's 24 elements are flat float4s [6t, 6t+6).
    const int b6 = 6 * t;
    const float s = ((ps[b6] + ps[b6 + 1]) + (ps[b6 + 2] + ps[b6 + 3]))
                  + (ps[b6 + 4] + ps[b6 + 5]);
    const float m = s * (2.0f / (float)KK);
    m_out[blockIdx.x * RPB + t] = m;

    // Deterministic block reduction of (m, m^2): warp shuffle + smem.
    float sm = m;
    float sq = m * m;
    #pragma unroll
    for (int off = 16; off > 0; off >>= 1) {
        sm += __shfl_down_sync(0xFFFFFFFFu, sm, off);
        sq += __shfl_down_sync(0xFFFFFFFFu, sq, off);
    }
    __shared__ float sh_m[BLOCK / 32];
    __shared__ float sh_q[BLOCK / 32];
    const int lane = t & 31;
    const int wid  = t >> 5;
    if (lane == 0) { sh_m[wid] = sm; sh_q[wid] = sq; }
    __syncthreads();
    if (wid == 0) {
        float tm = (lane < BLOCK / 32) ? sh_m[lane] : 0.0f;
        float tq = (lane < BLOCK / 32) ? sh_q[lane] : 0.0f;
        #pragma unroll
        for (int off = 4; off > 0; off >>= 1) {
            tm += __shfl_down_sync(0xFFFFFFFFu, tm, off);
            tq += __shfl_down_sync(0xFFFFFFFFu, tq, off);
        }
        if (lane == 0) {
            g_psum[blockIdx.x] = tm;
            g_psq[blockIdx.x]  = tq;
        }
    }
}

// ---------------------------------------------------------------------------
// Kernel 2: fused per-channel stats fold + BN affine + exact GELU, in place.
// Each block covers 256 float4 = 1024 consecutive elements of m — exactly one
// channel (c = blockIdx.x>>1 & 255). Warp 0 redundantly folds that channel's
// 64 (sum, sumsq) partials from L2 (fixed order -> deterministic), computes
// fused scale/shift, broadcasts via smem; then all 256 threads apply
// y = gelu(m*scale + shift). Replaces the serialized single-block k_stats.
// ---------------------------------------------------------------------------
__device__ __forceinline__ float gelu_exact(float y) {
    return 0.5f * y * (1.0f + erff(y * 0.70710678118654752f));
}

__global__ __launch_bounds__(BLOCK) void k_bn_gelu(float* __restrict__ m_io,
                                                   const float* __restrict__ gamma,
                                                   const float* __restrict__ beta) {
    const int t  = threadIdx.x;
    const int i4 = blockIdx.x * BLOCK + t;            // float4 index
    const int c  = (blockIdx.x >> 1) & (CC - 1);      // one channel per block

    // Issue the data load first so it overlaps the stats fold.
    float4 v = reinterpret_cast<const float4*>(m_io)[i4];

    __shared__ float sh_scale, sh_shift;
    if (t < 32) {
        // Partials for channel c live at ((b*CC + c)*8 + j), b in [0,8), j in [0,8).
        // Thread t folds b0=t>>3 (b in [0,4)) and b1=(t+32)>>3 (b in [4,8)), j=t&7.
        const int b0 = t >> 3,        j0 = t & 7;
        const int b1 = (t + 32) >> 3, j1 = t & 7;
        const int i0 = (b0 * CC + c) * 8 + j0;
        const int i1 = (b1 * CC + c) * 8 + j1;
        float sm = g_psum[i0] + g_psum[i1];
        float sq = g_psq[i0]  + g_psq[i1];
        #pragma unroll
        for (int off = 16; off > 0; off >>= 1) {
            sm += __shfl_down_sync(0xFFFFFFFFu, sm, off);
            sq += __shfl_down_sync(0xFFFFFFFFu, sq, off);
        }
        if (t == 0) {
            const float mean  = sm * INV_BN_COUNT;
            const float var   = sq * INV_BN_COUNT - mean * mean;  // biased (torch BN)
            const float scale = rsqrtf(var + BN_EPS) * gamma[c];
            sh_scale = scale;
            sh_shift = beta[c] - mean * scale;
        }
    }
    __syncthreads();
    const float scale = sh_scale;
    const float shift = sh_shift;

    v.x = gelu_exact(fmaf(v.x, scale, shift));
    v.y = gelu_exact(fmaf(v.y, scale, shift));
    v.z = gelu_exact(fmaf(v.z, scale, shift));
    v.w = gelu_exact(fmaf(v.w, scale, shift));
    reinterpret_cast<float4*>(m_io)[i4] = v;
}

// ---------------------------------------------------------------------------
extern "C" void kernel_launch(void* const* d_in, const int* in_sizes, int n_in,
                              void* d_out, int out_size) {
    const float* x     = (const float*)d_in[0];   // [B, C, N, K] f32
    const float* gamma = (const float*)d_in[1];   // [C]
    const float* beta  = (const float*)d_in[2];   // [C]
    float* out = (float*)d_out;                   // [B, C, N] f32

    k_reduce<<<NBLK, BLOCK>>>(x, out);
    k_bn_gelu<<<ROWS / 4 / BLOCK, BLOCK>>>(out, gamma, beta);
}